// round 9
// baseline (speedup 1.0000x reference)
#include <cuda_runtime.h>

#define BB 256
#define TT 1024
#define IDIM 2
#define HH 128
#define LL 4
#define MTOT (BB * TT)  // 262144

// Scratch (device globals: allocation-free). h ping-pong [B][T][H];
// xp padded by 4 rows for the distance-3 register-ring prefetch overrun.
__device__ float g_h0[BB * TT * HH];
__device__ float g_h1[BB * TT * HH];
__device__ float g_xp[BB * TT * HH + 4 * HH];

typedef unsigned long long ull;

__device__ __forceinline__ void ffma2(ull& acc, ull a, ull b) {
    asm("fma.rn.f32x2 %0, %1, %2, %0;" : "+l"(acc) : "l"(a), "l"(b));
}
__device__ __forceinline__ ull add2(ull a, ull b) {
    ull d;
    asm("add.rn.f32x2 %0, %1, %2;" : "=l"(d) : "l"(a), "l"(b));
    return d;
}
__device__ __forceinline__ ull dup2(float a) {
    ull d;
    asm("mov.b64 %0, {%1, %1};" : "=l"(d) : "f"(a));
    return d;
}
__device__ __forceinline__ ull pack2(float x, float y) {
    ull d;
    asm("mov.b64 %0, {%1, %2};" : "=l"(d) : "f"(x), "f"(y));
    return d;
}

// ---------------- layer-0 input projection (I=2, trivial) ----------------
__global__ void proj0_kernel(const float* __restrict__ x,
                             const float* __restrict__ W0,
                             const float* __restrict__ bih,
                             const float* __restrict__ bhh,
                             float* __restrict__ xp) {
    int idx = blockIdx.x * 256 + threadIdx.x;
    int m = idx >> 7, j = idx & 127;
    float2 xv = *(const float2*)(x + m * 2);
    float2 w = *(const float2*)(W0 + j * 2);
    xp[idx] = fmaf(xv.x, w.x, fmaf(xv.y, w.y, bih[j] + bhh[j]));
}

// ---------------- input-projection GEMM for layers 1..3 (R5 version) ----
__global__ void __launch_bounds__(256, 2)
gemm_xp(const float* __restrict__ A, const float* __restrict__ W,
        const float* __restrict__ bih, const float* __restrict__ bhh,
        float* __restrict__ xp) {
    __shared__ float As[2][128][17];
    __shared__ float Bs[2][16][132];

    const int tid = threadIdx.x;
    const int m0 = blockIdx.x * 128;
    const int tx = tid & 15, ty = tid >> 4;
    const int n0 = tx * 8, mt = ty * 8;

    float4 av[2], bv[2];
#pragma unroll
    for (int it = 0; it < 2; it++) {
        int idx = tid + it * 256;
        int mm = idx >> 2, kq = idx & 3;
        av[it] = *(const float4*)(A + (size_t)(m0 + mm) * HH + kq * 4);
        bv[it] = *(const float4*)(W + (size_t)mm * HH + kq * 4);
    }
#pragma unroll
    for (int it = 0; it < 2; it++) {
        int idx = tid + it * 256;
        int mm = idx >> 2, kq = idx & 3;
        As[0][mm][kq * 4 + 0] = av[it].x;
        As[0][mm][kq * 4 + 1] = av[it].y;
        As[0][mm][kq * 4 + 2] = av[it].z;
        As[0][mm][kq * 4 + 3] = av[it].w;
        Bs[0][kq * 4 + 0][mm] = bv[it].x;
        Bs[0][kq * 4 + 1][mm] = bv[it].y;
        Bs[0][kq * 4 + 2][mm] = bv[it].z;
        Bs[0][kq * 4 + 3][mm] = bv[it].w;
    }
    __syncthreads();

    ull acc[8][4];
#pragma unroll
    for (int i = 0; i < 8; i++)
#pragma unroll
        for (int p = 0; p < 4; p++) acc[i][p] = 0ULL;

    int buf = 0;
    for (int kc = 0; kc < 8; kc++) {
        if (kc < 7) {
#pragma unroll
            for (int it = 0; it < 2; it++) {
                int idx = tid + it * 256;
                int mm = idx >> 2, kq = idx & 3;
                av[it] = *(const float4*)(A + (size_t)(m0 + mm) * HH +
                                          (kc + 1) * 16 + kq * 4);
                bv[it] = *(const float4*)(W + (size_t)mm * HH + (kc + 1) * 16 +
                                          kq * 4);
            }
        }
#pragma unroll
        for (int k = 0; k < 16; k++) {
            const ulonglong2* bp = (const ulonglong2*)&Bs[buf][k][n0];
            ulonglong2 u0 = bp[0], u1 = bp[1];
            ull ad[8];
#pragma unroll
            for (int i = 0; i < 8; i++) ad[i] = dup2(As[buf][mt + i][k]);
#pragma unroll
            for (int i = 0; i < 8; i++) {
                ffma2(acc[i][0], ad[i], u0.x);
                ffma2(acc[i][1], ad[i], u0.y);
                ffma2(acc[i][2], ad[i], u1.x);
                ffma2(acc[i][3], ad[i], u1.y);
            }
        }
        if (kc < 7) {
#pragma unroll
            for (int it = 0; it < 2; it++) {
                int idx = tid + it * 256;
                int mm = idx >> 2, kq = idx & 3;
                As[buf ^ 1][mm][kq * 4 + 0] = av[it].x;
                As[buf ^ 1][mm][kq * 4 + 1] = av[it].y;
                As[buf ^ 1][mm][kq * 4 + 2] = av[it].z;
                As[buf ^ 1][mm][kq * 4 + 3] = av[it].w;
                Bs[buf ^ 1][kq * 4 + 0][mm] = bv[it].x;
                Bs[buf ^ 1][kq * 4 + 1][mm] = bv[it].y;
                Bs[buf ^ 1][kq * 4 + 2][mm] = bv[it].z;
                Bs[buf ^ 1][kq * 4 + 3][mm] = bv[it].w;
            }
            __syncthreads();
            buf ^= 1;
        }
    }

    ull biasp[4];
#pragma unroll
    for (int p = 0; p < 4; p++) {
        float b0 = bih[n0 + 2 * p] + bhh[n0 + 2 * p];
        float b1 = bih[n0 + 2 * p + 1] + bhh[n0 + 2 * p + 1];
        biasp[p] = pack2(b0, b1);
    }
#pragma unroll
    for (int i = 0; i < 8; i++) {
        ull o0 = add2(acc[i][0], biasp[0]);
        ull o1 = add2(acc[i][1], biasp[1]);
        ull o2 = add2(acc[i][2], biasp[2]);
        ull o3 = add2(acc[i][3], biasp[3]);
        float* dst = xp + (size_t)(m0 + mt + i) * HH + n0;
        *(ulonglong2*)dst = make_ulonglong2(o0, o1);
        *(ulonglong2*)(dst + 4) = make_ulonglong2(o2, o3);
    }
}

// ---------------- recurrent scan: R5 topology + k-split lane pairs ------
// 256 CTAs (1 batch row each) x 256 threads; 2 CTAs co-resident per SM
// (anti-phased domains). Thread (j = tid>>1, s = tid&1) holds half the
// weight row Whh[j, s*64..s*64+63] in 32 packed f32x2 regs -> per step:
// 16 LDS.128 + 32 FFMA2 (half R5's serial chain). Halves combine with one
// shfl_xor(1) (lane pairs adjacent). h halves live at smem offsets 0 / 68
// floats so even/odd lanes hit disjoint banks. One __syncthreads per step.
// Final layer: no hidden stores, FC (C=1) fused into the epilogue.
__global__ void __launch_bounds__(256, 2)
rnn_scan(const float* __restrict__ xp, float* __restrict__ out_h,
         const float* __restrict__ Whh, int store_all,
         const float* __restrict__ fcw, const float* __restrict__ fcb,
         float* __restrict__ fc_out) {
    __shared__ __align__(16) float hbuf[2][136];  // halves at +0 / +68
    __shared__ float red[8];

    const int tid = threadIdx.x;
    const int j = tid >> 1;
    const int s = tid & 1;
    const int b = blockIdx.x;

    // half weight row, 32 packed f32x2 pairs
    ull w[32];
    {
        const ull* wp = (const ull*)(Whh + j * HH + s * 64);
#pragma unroll
        for (int i = 0; i < 32; i++) w[i] = wp[i];
    }

    for (int i = tid; i < 272; i += 256) ((float*)hbuf)[i] = 0.f;

    const float* xptr = xp + (size_t)b * TT * HH + j;
    float* optr = out_h + (size_t)b * TT * HH + j;
    float xqa = 0.f, xqb = 0.f, xqc = 0.f;
    if (s == 0) {
        xqa = xptr[0];
        xqb = xptr[HH];
        xqc = xptr[2 * HH];
    }
    const float* xf = xptr + 3 * HH;  // padded scratch: safe overrun
    const int jofs = (j < 64) ? j : j + 4;  // write slot in 68-offset layout
    __syncthreads();

    float lh = 0.f;
    int buf = 0;
    for (int t = 0; t < TT; t++) {
        float xn = 0.f;
        if (s == 0) xn = *xf;  // xp(t+3), lands 3 steps out
        xf += HH;

        const ulonglong2* hp = (const ulonglong2*)&hbuf[buf][s * 68];
        ull a0 = 0ULL, a1 = 0ULL, a2 = 0ULL, a3 = 0ULL;
#pragma unroll
        for (int q = 0; q < 16; q += 4) {
            ulonglong2 u0 = hp[q];      // broadcast LDS.128 (2 addrs/warp,
            ulonglong2 u1 = hp[q + 1];  //  disjoint banks via +68 offset)
            ulonglong2 u2 = hp[q + 2];
            ulonglong2 u3 = hp[q + 3];
            ffma2(a0, u0.x, w[2 * q + 0]);
            ffma2(a0, u0.y, w[2 * q + 1]);
            ffma2(a1, u1.x, w[2 * q + 2]);
            ffma2(a1, u1.y, w[2 * q + 3]);
            ffma2(a2, u2.x, w[2 * q + 4]);
            ffma2(a2, u2.y, w[2 * q + 5]);
            ffma2(a3, u3.x, w[2 * q + 6]);
            ffma2(a3, u3.y, w[2 * q + 7]);
        }
        ull sA = add2(add2(a0, a1), add2(a2, a3));
        float2 f = *(float2*)&sA;
        float sum = f.x + f.y;
        sum += __shfl_xor_sync(0xffffffffu, sum, 1);  // combine k-halves
        float h = fmaxf(sum + xqa, 0.f);

        if (s == 0) {
            hbuf[buf ^ 1][jofs] = h;
            if (store_all) optr[0] = h;
            lh = h;
            xqa = xqb;
            xqb = xqc;
            xqc = xn;
        }
        optr += HH;
        buf ^= 1;
        __syncthreads();
    }

    if (fc_out) {
        float v = (s == 0) ? lh * fcw[j] : 0.f;
#pragma unroll
        for (int o = 16; o > 0; o >>= 1)
            v += __shfl_down_sync(0xffffffffu, v, o);
        if ((tid & 31) == 0) red[tid >> 5] = v;
        __syncthreads();
        if (tid == 0) {
            float rsum = fcb[0];
#pragma unroll
            for (int i = 0; i < 8; i++) rsum += red[i];
            fc_out[b] = rsum;
        }
    }
}

extern "C" void kernel_launch(void* const* d_in, const int* in_sizes, int n_in,
                              void* d_out, int out_size) {
    const float* x    = (const float*)d_in[0];  // [B,T,I]
    const float* Wih0 = (const float*)d_in[1];  // [H,I]
    const float* WihL = (const float*)d_in[2];  // [L-1,H,H]
    const float* Whh  = (const float*)d_in[3];  // [L,H,H]
    const float* bih  = (const float*)d_in[4];  // [L,H]
    const float* bhh  = (const float*)d_in[5];  // [L,H]
    const float* fcw  = (const float*)d_in[6];  // [C,H]
    const float* fcb  = (const float*)d_in[7];  // [C]
    float* out = (float*)d_out;                 // [B,C] = [256,1]

    float *h0, *h1, *xpb;
    cudaGetSymbolAddress((void**)&h0, g_h0);
    cudaGetSymbolAddress((void**)&h1, g_h1);
    cudaGetSymbolAddress((void**)&xpb, g_xp);

    const int HW = HH * HH;
    // layer 0
    proj0_kernel<<<(MTOT * HH) / 256, 256>>>(x, Wih0, bih, bhh, xpb);
    rnn_scan<<<BB, 256>>>(xpb, h0, Whh + 0 * HW, 1, nullptr, nullptr, nullptr);
    // layer 1
    gemm_xp<<<MTOT / 128, 256>>>(h0, WihL + 0 * HW, bih + 1 * HH, bhh + 1 * HH,
                                 xpb);
    rnn_scan<<<BB, 256>>>(xpb, h1, Whh + 1 * HW, 1, nullptr, nullptr, nullptr);
    // layer 2
    gemm_xp<<<MTOT / 128, 256>>>(h1, WihL + 1 * HW, bih + 2 * HH, bhh + 2 * HH,
                                 xpb);
    rnn_scan<<<BB, 256>>>(xpb, h0, Whh + 2 * HW, 1, nullptr, nullptr, nullptr);
    // layer 3: no hidden stores, FC fused
    gemm_xp<<<MTOT / 128, 256>>>(h0, WihL + 2 * HW, bih + 3 * HH, bhh + 3 * HH,
                                 xpb);
    rnn_scan<<<BB, 256>>>(xpb, h1, Whh + 3 * HW, 0, fcw, fcb, out);
}

// round 10
// speedup vs baseline: 1.0900x; 1.0900x over previous
#include <cuda_runtime.h>

#define BB 256
#define TT 1024
#define IDIM 2
#define HH 128
#define LL 4
#define MTOT (BB * TT)  // 262144

// Scratch (device globals: allocation-free). h ping-pong [B][T][H];
// xp padded by 8 rows for the block-prefetch overrun (reads t+4..t+7).
__device__ float g_h0[BB * TT * HH];
__device__ float g_h1[BB * TT * HH];
__device__ float g_xp[BB * TT * HH + 8 * HH];

typedef unsigned long long ull;

__device__ __forceinline__ void ffma2(ull& acc, ull a, ull b) {
    asm("fma.rn.f32x2 %0, %1, %2, %0;" : "+l"(acc) : "l"(a), "l"(b));
}
__device__ __forceinline__ ull add2(ull a, ull b) {
    ull d;
    asm("add.rn.f32x2 %0, %1, %2;" : "=l"(d) : "l"(a), "l"(b));
    return d;
}
__device__ __forceinline__ ull dup2(float a) {
    ull d;
    asm("mov.b64 %0, {%1, %1};" : "=l"(d) : "f"(a));
    return d;
}
__device__ __forceinline__ ull pack2(float x, float y) {
    ull d;
    asm("mov.b64 %0, {%1, %2};" : "=l"(d) : "f"(x), "f"(y));
    return d;
}

// ---------------- layer-0 input projection (I=2, trivial) ----------------
__global__ void proj0_kernel(const float* __restrict__ x,
                             const float* __restrict__ W0,
                             const float* __restrict__ bih,
                             const float* __restrict__ bhh,
                             float* __restrict__ xp) {
    int idx = blockIdx.x * 256 + threadIdx.x;
    int m = idx >> 7, j = idx & 127;
    float2 xv = *(const float2*)(x + m * 2);
    float2 w = *(const float2*)(W0 + j * 2);
    xp[idx] = fmaf(xv.x, w.x, fmaf(xv.y, w.y, bih[j] + bhh[j]));
}

// ---------------- input-projection GEMM for layers 1..3 (proven R5) -----
__global__ void __launch_bounds__(256, 2)
gemm_xp(const float* __restrict__ A, const float* __restrict__ W,
        const float* __restrict__ bih, const float* __restrict__ bhh,
        float* __restrict__ xp) {
    __shared__ float As[2][128][17];
    __shared__ float Bs[2][16][132];

    const int tid = threadIdx.x;
    const int m0 = blockIdx.x * 128;
    const int tx = tid & 15, ty = tid >> 4;
    const int n0 = tx * 8, mt = ty * 8;

    float4 av[2], bv[2];
#pragma unroll
    for (int it = 0; it < 2; it++) {
        int idx = tid + it * 256;
        int mm = idx >> 2, kq = idx & 3;
        av[it] = *(const float4*)(A + (size_t)(m0 + mm) * HH + kq * 4);
        bv[it] = *(const float4*)(W + (size_t)mm * HH + kq * 4);
    }
#pragma unroll
    for (int it = 0; it < 2; it++) {
        int idx = tid + it * 256;
        int mm = idx >> 2, kq = idx & 3;
        As[0][mm][kq * 4 + 0] = av[it].x;
        As[0][mm][kq * 4 + 1] = av[it].y;
        As[0][mm][kq * 4 + 2] = av[it].z;
        As[0][mm][kq * 4 + 3] = av[it].w;
        Bs[0][kq * 4 + 0][mm] = bv[it].x;
        Bs[0][kq * 4 + 1][mm] = bv[it].y;
        Bs[0][kq * 4 + 2][mm] = bv[it].z;
        Bs[0][kq * 4 + 3][mm] = bv[it].w;
    }
    __syncthreads();

    ull acc[8][4];
#pragma unroll
    for (int i = 0; i < 8; i++)
#pragma unroll
        for (int p = 0; p < 4; p++) acc[i][p] = 0ULL;

    int buf = 0;
    for (int kc = 0; kc < 8; kc++) {
        if (kc < 7) {
#pragma unroll
            for (int it = 0; it < 2; it++) {
                int idx = tid + it * 256;
                int mm = idx >> 2, kq = idx & 3;
                av[it] = *(const float4*)(A + (size_t)(m0 + mm) * HH +
                                          (kc + 1) * 16 + kq * 4);
                bv[it] = *(const float4*)(W + (size_t)mm * HH + (kc + 1) * 16 +
                                          kq * 4);
            }
        }
#pragma unroll
        for (int k = 0; k < 16; k++) {
            const ulonglong2* bp = (const ulonglong2*)&Bs[buf][k][n0];
            ulonglong2 u0 = bp[0], u1 = bp[1];
            ull ad[8];
#pragma unroll
            for (int i = 0; i < 8; i++) ad[i] = dup2(As[buf][mt + i][k]);
#pragma unroll
            for (int i = 0; i < 8; i++) {
                ffma2(acc[i][0], ad[i], u0.x);
                ffma2(acc[i][1], ad[i], u0.y);
                ffma2(acc[i][2], ad[i], u1.x);
                ffma2(acc[i][3], ad[i], u1.y);
            }
        }
        if (kc < 7) {
#pragma unroll
            for (int it = 0; it < 2; it++) {
                int idx = tid + it * 256;
                int mm = idx >> 2, kq = idx & 3;
                As[buf ^ 1][mm][kq * 4 + 0] = av[it].x;
                As[buf ^ 1][mm][kq * 4 + 1] = av[it].y;
                As[buf ^ 1][mm][kq * 4 + 2] = av[it].z;
                As[buf ^ 1][mm][kq * 4 + 3] = av[it].w;
                Bs[buf ^ 1][kq * 4 + 0][mm] = bv[it].x;
                Bs[buf ^ 1][kq * 4 + 1][mm] = bv[it].y;
                Bs[buf ^ 1][kq * 4 + 2][mm] = bv[it].z;
                Bs[buf ^ 1][kq * 4 + 3][mm] = bv[it].w;
            }
            __syncthreads();
            buf ^= 1;
        }
    }

    ull biasp[4];
#pragma unroll
    for (int p = 0; p < 4; p++) {
        float b0 = bih[n0 + 2 * p] + bhh[n0 + 2 * p];
        float b1 = bih[n0 + 2 * p + 1] + bhh[n0 + 2 * p + 1];
        biasp[p] = pack2(b0, b1);
    }
#pragma unroll
    for (int i = 0; i < 8; i++) {
        ull o0 = add2(acc[i][0], biasp[0]);
        ull o1 = add2(acc[i][1], biasp[1]);
        ull o2 = add2(acc[i][2], biasp[2]);
        ull o3 = add2(acc[i][3], biasp[3]);
        float* dst = xp + (size_t)(m0 + mt + i) * HH + n0;
        *(ulonglong2*)dst = make_ulonglong2(o0, o1);
        *(ulonglong2*)(dst + 4) = make_ulonglong2(o2, o3);
    }
}

// ---------------- recurrent scan: R5 topology + pipelined xp ring -------
// 256 CTAs (1 batch row each) x 128 threads; 2 CTAs co-resident per SM
// (anti-phased 4-warp domains). Thread j holds the FULL row Whh[j,:] in
// 64 packed f32x2 regs; 8 accumulator chains, LDS in groups of 4 (16 live
// regs/group -> ptxas can pipeline ahead). t-loop unrolled x4 with a block
// prefetch: 4 independent LDGs fetch xp(t+4..t+7) at block start and are
// consumed a full ~4-step distance later -> no per-step LDG scoreboard
// stall (the R5 ring waited on a ~600cyc DRAM load EVERY step).
template <bool STORE, bool FC>
__global__ void __launch_bounds__(128, 2)
rnn_scan(const float* __restrict__ xp, float* __restrict__ out_h,
         const float* __restrict__ Whh, const float* __restrict__ fcw,
         const float* __restrict__ fcb, float* __restrict__ fc_out) {
    __shared__ __align__(16) float hbuf[2][HH];
    __shared__ float red[4];

    const int j = threadIdx.x;
    const int b = blockIdx.x;

    // full weight row, packed as 64 f32x2 pairs
    ull w[64];
    {
        const ull* wp = (const ull*)(Whh + j * HH);
#pragma unroll
        for (int i = 0; i < 64; i++) w[i] = wp[i];
    }

    hbuf[0][j] = 0.f;  // h(-1) = 0

    const float* xptr = xp + (size_t)b * TT * HH + j;
    float* optr = out_h + (size_t)b * TT * HH + j;

    float cur[4], nxt[4];
#pragma unroll
    for (int i = 0; i < 4; i++) cur[i] = xptr[i * HH];
    const float* xf = xptr + 4 * HH;  // padded scratch: safe overrun
    __syncthreads();

    float lh = 0.f;
    int buf = 0;
    for (int t = 0; t < TT; t += 4) {
        // block prefetch: 4 independent LDGs for steps t+4..t+7 (MLP=4)
#pragma unroll
        for (int i = 0; i < 4; i++) nxt[i] = xf[i * HH];
        xf += 4 * HH;

#pragma unroll
        for (int u = 0; u < 4; u++) {
            const ulonglong2* hp = (const ulonglong2*)hbuf[buf];
            ull a0 = 0ULL, a1 = 0ULL, a2 = 0ULL, a3 = 0ULL;
            ull a4 = 0ULL, a5 = 0ULL, a6 = 0ULL, a7 = 0ULL;
#pragma unroll
            for (int q = 0; q < 32; q += 4) {
                ulonglong2 u0 = hp[q];      // broadcast LDS.128
                ulonglong2 u1 = hp[q + 1];
                ulonglong2 u2 = hp[q + 2];
                ulonglong2 u3 = hp[q + 3];
                ffma2(a0, u0.x, w[2 * q + 0]);
                ffma2(a1, u0.y, w[2 * q + 1]);
                ffma2(a2, u1.x, w[2 * q + 2]);
                ffma2(a3, u1.y, w[2 * q + 3]);
                ffma2(a4, u2.x, w[2 * q + 4]);
                ffma2(a5, u2.y, w[2 * q + 5]);
                ffma2(a6, u3.x, w[2 * q + 6]);
                ffma2(a7, u3.y, w[2 * q + 7]);
            }
            ull s = add2(add2(add2(a0, a1), add2(a2, a3)),
                         add2(add2(a4, a5), add2(a6, a7)));
            float2 f = *(float2*)&s;
            float h = fmaxf(f.x + f.y + cur[u], 0.f);

            hbuf[buf ^ 1][j] = h;
            if (STORE) {
                optr[0] = h;  // warp writes 128B coalesced
                optr += HH;
            }
            if (FC) lh = h;
            buf ^= 1;
            __syncthreads();
        }
        // rotate ring once per block; loads issued ~4 steps ago have landed
#pragma unroll
        for (int i = 0; i < 4; i++) cur[i] = nxt[i];
    }

    if (FC) {
        float v = lh * fcw[j];
#pragma unroll
        for (int o = 16; o > 0; o >>= 1)
            v += __shfl_down_sync(0xffffffffu, v, o);
        if ((j & 31) == 0) red[j >> 5] = v;
        __syncthreads();
        if (j == 0) fc_out[b] = red[0] + red[1] + red[2] + red[3] + fcb[0];
    }
}

extern "C" void kernel_launch(void* const* d_in, const int* in_sizes, int n_in,
                              void* d_out, int out_size) {
    const float* x    = (const float*)d_in[0];  // [B,T,I]
    const float* Wih0 = (const float*)d_in[1];  // [H,I]
    const float* WihL = (const float*)d_in[2];  // [L-1,H,H]
    const float* Whh  = (const float*)d_in[3];  // [L,H,H]
    const float* bih  = (const float*)d_in[4];  // [L,H]
    const float* bhh  = (const float*)d_in[5];  // [L,H]
    const float* fcw  = (const float*)d_in[6];  // [C,H]
    const float* fcb  = (const float*)d_in[7];  // [C]
    float* out = (float*)d_out;                 // [B,C] = [256,1]

    float *h0, *h1, *xpb;
    cudaGetSymbolAddress((void**)&h0, g_h0);
    cudaGetSymbolAddress((void**)&h1, g_h1);
    cudaGetSymbolAddress((void**)&xpb, g_xp);

    const int HW = HH * HH;
    // layer 0
    proj0_kernel<<<(MTOT * HH) / 256, 256>>>(x, Wih0, bih, bhh, xpb);
    rnn_scan<true, false><<<BB, 128>>>(xpb, h0, Whh + 0 * HW, nullptr, nullptr,
                                       nullptr);
    // layer 1
    gemm_xp<<<MTOT / 128, 256>>>(h0, WihL + 0 * HW, bih + 1 * HH, bhh + 1 * HH,
                                 xpb);
    rnn_scan<true, false><<<BB, 128>>>(xpb, h1, Whh + 1 * HW, nullptr, nullptr,
                                       nullptr);
    // layer 2
    gemm_xp<<<MTOT / 128, 256>>>(h1, WihL + 1 * HW, bih + 2 * HH, bhh + 2 * HH,
                                 xpb);
    rnn_scan<true, false><<<BB, 128>>>(xpb, h0, Whh + 2 * HW, nullptr, nullptr,
                                       nullptr);
    // layer 3: no hidden stores, FC fused into the scan epilogue
    gemm_xp<<<MTOT / 128, 256>>>(h0, WihL + 2 * HW, bih + 3 * HH, bhh + 3 * HH,
                                 xpb);
    rnn_scan<false, true><<<BB, 128>>>(xpb, nullptr, Whh + 3 * HW, fcw, fcb,
                                       out);
}

// round 12
// speedup vs baseline: 1.2172x; 1.1167x over previous
#include <cuda_runtime.h>
#include <cstdint>

#define BB 256
#define TT 1024
#define IDIM 2
#define HH 128
#define LL 4
#define MTOT (BB * TT)  // 262144

// Scratch (device globals: allocation-free). h ping-pong [B][T][H];
// xp padded by 8 rows for the depth-7 cp.async prefetch overrun.
__device__ float g_h0[BB * TT * HH];
__device__ float g_h1[BB * TT * HH];
__device__ float g_xp[BB * TT * HH + 8 * HH];

typedef unsigned long long ull;
typedef unsigned int u32;

__device__ __forceinline__ void ffma2(ull& acc, ull a, ull b) {
    asm("fma.rn.f32x2 %0, %1, %2, %0;" : "+l"(acc) : "l"(a), "l"(b));
}
__device__ __forceinline__ ull add2(ull a, ull b) {
    ull d;
    asm("add.rn.f32x2 %0, %1, %2;" : "=l"(d) : "l"(a), "l"(b));
    return d;
}
__device__ __forceinline__ ull dup2(float a) {
    ull d;
    asm("mov.b64 %0, {%1, %1};" : "=l"(d) : "f"(a));
    return d;
}
__device__ __forceinline__ ull pack2(float x, float y) {
    ull d;
    asm("mov.b64 %0, {%1, %2};" : "=l"(d) : "f"(x), "f"(y));
    return d;
}
__device__ __forceinline__ void cp_async4(u32 saddr, const float* gptr) {
    asm volatile("cp.async.ca.shared.global [%0], [%1], 4;" ::"r"(saddr),
                 "l"(gptr)
                 : "memory");
}
__device__ __forceinline__ void cp_commit() {
    asm volatile("cp.async.commit_group;" ::: "memory");
}
__device__ __forceinline__ void cp_wait6() {
    asm volatile("cp.async.wait_group 6;" ::: "memory");
}

// ---------------- layer-0 input projection (I=2, trivial) ----------------
__global__ void proj0_kernel(const float* __restrict__ x,
                             const float* __restrict__ W0,
                             const float* __restrict__ bih,
                             const float* __restrict__ bhh,
                             float* __restrict__ xp) {
    int idx = blockIdx.x * 256 + threadIdx.x;
    int m = idx >> 7, j = idx & 127;
    float2 xv = *(const float2*)(x + m * 2);
    float2 w = *(const float2*)(W0 + j * 2);
    xp[idx] = fmaf(xv.x, w.x, fmaf(xv.y, w.y, bih[j] + bhh[j]));
}

// ---------------- input-projection GEMM for layers 1..3 (proven R5) -----
__global__ void __launch_bounds__(256, 2)
gemm_xp(const float* __restrict__ A, const float* __restrict__ W,
        const float* __restrict__ bih, const float* __restrict__ bhh,
        float* __restrict__ xp) {
    __shared__ float As[2][128][17];
    __shared__ float Bs[2][16][132];

    const int tid = threadIdx.x;
    const int m0 = blockIdx.x * 128;
    const int tx = tid & 15, ty = tid >> 4;
    const int n0 = tx * 8, mt = ty * 8;

    float4 av[2], bv[2];
#pragma unroll
    for (int it = 0; it < 2; it++) {
        int idx = tid + it * 256;
        int mm = idx >> 2, kq = idx & 3;
        av[it] = *(const float4*)(A + (size_t)(m0 + mm) * HH + kq * 4);
        bv[it] = *(const float4*)(W + (size_t)mm * HH + kq * 4);
    }
#pragma unroll
    for (int it = 0; it < 2; it++) {
        int idx = tid + it * 256;
        int mm = idx >> 2, kq = idx & 3;
        As[0][mm][kq * 4 + 0] = av[it].x;
        As[0][mm][kq * 4 + 1] = av[it].y;
        As[0][mm][kq * 4 + 2] = av[it].z;
        As[0][mm][kq * 4 + 3] = av[it].w;
        Bs[0][kq * 4 + 0][mm] = bv[it].x;
        Bs[0][kq * 4 + 1][mm] = bv[it].y;
        Bs[0][kq * 4 + 2][mm] = bv[it].z;
        Bs[0][kq * 4 + 3][mm] = bv[it].w;
    }
    __syncthreads();

    ull acc[8][4];
#pragma unroll
    for (int i = 0; i < 8; i++)
#pragma unroll
        for (int p = 0; p < 4; p++) acc[i][p] = 0ULL;

    int buf = 0;
    for (int kc = 0; kc < 8; kc++) {
        if (kc < 7) {
#pragma unroll
            for (int it = 0; it < 2; it++) {
                int idx = tid + it * 256;
                int mm = idx >> 2, kq = idx & 3;
                av[it] = *(const float4*)(A + (size_t)(m0 + mm) * HH +
                                          (kc + 1) * 16 + kq * 4);
                bv[it] = *(const float4*)(W + (size_t)mm * HH + (kc + 1) * 16 +
                                          kq * 4);
            }
        }
#pragma unroll
        for (int k = 0; k < 16; k++) {
            const ulonglong2* bp = (const ulonglong2*)&Bs[buf][k][n0];
            ulonglong2 u0 = bp[0], u1 = bp[1];
            ull ad[8];
#pragma unroll
            for (int i = 0; i < 8; i++) ad[i] = dup2(As[buf][mt + i][k]);
#pragma unroll
            for (int i = 0; i < 8; i++) {
                ffma2(acc[i][0], ad[i], u0.x);
                ffma2(acc[i][1], ad[i], u0.y);
                ffma2(acc[i][2], ad[i], u1.x);
                ffma2(acc[i][3], ad[i], u1.y);
            }
        }
        if (kc < 7) {
#pragma unroll
            for (int it = 0; it < 2; it++) {
                int idx = tid + it * 256;
                int mm = idx >> 2, kq = idx & 3;
                As[buf ^ 1][mm][kq * 4 + 0] = av[it].x;
                As[buf ^ 1][mm][kq * 4 + 1] = av[it].y;
                As[buf ^ 1][mm][kq * 4 + 2] = av[it].z;
                As[buf ^ 1][mm][kq * 4 + 3] = av[it].w;
                Bs[buf ^ 1][kq * 4 + 0][mm] = bv[it].x;
                Bs[buf ^ 1][kq * 4 + 1][mm] = bv[it].y;
                Bs[buf ^ 1][kq * 4 + 2][mm] = bv[it].z;
                Bs[buf ^ 1][kq * 4 + 3][mm] = bv[it].w;
            }
            __syncthreads();
            buf ^= 1;
        }
    }

    ull biasp[4];
#pragma unroll
    for (int p = 0; p < 4; p++) {
        float b0 = bih[n0 + 2 * p] + bhh[n0 + 2 * p];
        float b1 = bih[n0 + 2 * p + 1] + bhh[n0 + 2 * p + 1];
        biasp[p] = pack2(b0, b1);
    }
#pragma unroll
    for (int i = 0; i < 8; i++) {
        ull o0 = add2(acc[i][0], biasp[0]);
        ull o1 = add2(acc[i][1], biasp[1]);
        ull o2 = add2(acc[i][2], biasp[2]);
        ull o3 = add2(acc[i][3], biasp[3]);
        float* dst = xp + (size_t)(m0 + mt + i) * HH + n0;
        *(ulonglong2*)dst = make_ulonglong2(o0, o1);
        *(ulonglong2*)(dst + 4) = make_ulonglong2(o2, o3);
    }
}

// ---------------- recurrent scan: exact R5 body + cp.async xp pipeline --
// 256 CTAs (1 batch row each) x 128 threads; 2 CTAs co-resident per SM
// (anti-phased 4-warp domains). Thread j holds the FULL row Whh[j,:] in
// 64 packed f32x2 regs (R5's 4-accumulator dot body). xp arrives through
// a depth-7 cp.async smem ring: the global load has NO destination
// register, so the per-step DRAM scoreboard stall that bounded R5/R6/R9
// disappears; consume is a 29-cyc LDS of the thread's own slot ~2000 cyc
// after issue. One __syncthreads per step. Final layer: no hidden stores,
// FC (C=1) fused into the epilogue.
template <bool STORE, bool FC>
__global__ void __launch_bounds__(128, 2)
rnn_scan(const float* __restrict__ xp, float* __restrict__ out_h,
         const float* __restrict__ Whh, const float* __restrict__ fcw,
         const float* __restrict__ fcb, float* __restrict__ fc_out) {
    __shared__ __align__(16) float hbuf[2][HH];
    __shared__ __align__(16) float xpring[8][HH];
    __shared__ float red[4];

    const int j = threadIdx.x;
    const int b = blockIdx.x;

    // full weight row, packed as 64 f32x2 pairs
    ull w[64];
    {
        const ull* wp = (const ull*)(Whh + j * HH);
#pragma unroll
        for (int i = 0; i < 64; i++) w[i] = wp[i];
    }

    hbuf[0][j] = 0.f;  // h(-1) = 0

    const float* xptr = xp + (size_t)b * TT * HH + j;
    float* optr = out_h + (size_t)b * TT * HH + j;

    // prefill: 7 cp.async groups for steps 0..6 (per-thread own slot)
    u32 ring_s[8];
#pragma unroll
    for (int i = 0; i < 8; i++)
        ring_s[i] = (u32)__cvta_generic_to_shared(&xpring[i][j]);
#pragma unroll
    for (int i = 0; i < 7; i++) {
        cp_async4(ring_s[i], xptr + (size_t)i * HH);
        cp_commit();
    }
    const float* xf = xptr + 7 * HH;  // next prefetch target (t+7)
    __syncthreads();

    float lh = 0.f;
    int buf = 0;
    for (int t = 0; t < TT; t++) {
        cp_wait6();                   // group t complete
        float xv = xpring[t & 7][j];  // own slot: no cross-thread dep

        const ulonglong2* hp = (const ulonglong2*)hbuf[buf];
        ull a0 = 0ULL, a1 = 0ULL, a2 = 0ULL, a3 = 0ULL;
#pragma unroll
        for (int q = 0; q < 32; q += 4) {
            ulonglong2 u0 = hp[q];      // broadcast LDS.128
            ulonglong2 u1 = hp[q + 1];
            ulonglong2 u2 = hp[q + 2];
            ulonglong2 u3 = hp[q + 3];
            ffma2(a0, u0.x, w[2 * q + 0]);
            ffma2(a0, u0.y, w[2 * q + 1]);
            ffma2(a1, u1.x, w[2 * q + 2]);
            ffma2(a1, u1.y, w[2 * q + 3]);
            ffma2(a2, u2.x, w[2 * q + 4]);
            ffma2(a2, u2.y, w[2 * q + 5]);
            ffma2(a3, u3.x, w[2 * q + 6]);
            ffma2(a3, u3.y, w[2 * q + 7]);
        }
        ull s = add2(add2(a0, a1), add2(a2, a3));
        float2 f = *(float2*)&s;
        float h = fmaxf(f.x + f.y + xv, 0.f);

        hbuf[buf ^ 1][j] = h;
        if (STORE) {
            optr[0] = h;  // warp writes 128B coalesced
            optr += HH;
        }
        if (FC) lh = h;

        // prefetch xp(t+7) into slot (t+7)&7 == (t-1)&7 (read last iter)
        cp_async4(ring_s[(t + 7) & 7], xf);
        cp_commit();
        xf += HH;  // padded scratch: safe overrun

        buf ^= 1;
        __syncthreads();
    }

    if (FC) {
        float v = lh * fcw[j];
#pragma unroll
        for (int o = 16; o > 0; o >>= 1)
            v += __shfl_down_sync(0xffffffffu, v, o);
        if ((j & 31) == 0) red[j >> 5] = v;
        __syncthreads();
        if (j == 0) fc_out[b] = red[0] + red[1] + red[2] + red[3] + fcb[0];
    }
}

extern "C" void kernel_launch(void* const* d_in, const int* in_sizes, int n_in,
                              void* d_out, int out_size) {
    const float* x    = (const float*)d_in[0];  // [B,T,I]
    const float* Wih0 = (const float*)d_in[1];  // [H,I]
    const float* WihL = (const float*)d_in[2];  // [L-1,H,H]
    const float* Whh  = (const float*)d_in[3];  // [L,H,H]
    const float* bih  = (const float*)d_in[4];  // [L,H]
    const float* bhh  = (const float*)d_in[5];  // [L,H]
    const float* fcw  = (const float*)d_in[6];  // [C,H]
    const float* fcb  = (const float*)d_in[7];  // [C]
    float* out = (float*)d_out;                 // [B,C] = [256,1]

    float *h0, *h1, *xpb;
    cudaGetSymbolAddress((void**)&h0, g_h0);
    cudaGetSymbolAddress((void**)&h1, g_h1);
    cudaGetSymbolAddress((void**)&xpb, g_xp);

    const int HW = HH * HH;
    // layer 0
    proj0_kernel<<<(MTOT * HH) / 256, 256>>>(x, Wih0, bih, bhh, xpb);
    rnn_scan<true, false><<<BB, 128>>>(xpb, h0, Whh + 0 * HW, nullptr, nullptr,
                                       nullptr);
    // layer 1
    gemm_xp<<<MTOT / 128, 256>>>(h0, WihL + 0 * HW, bih + 1 * HH, bhh + 1 * HH,
                                 xpb);
    rnn_scan<true, false><<<BB, 128>>>(xpb, h1, Whh + 1 * HW, nullptr, nullptr,
                                       nullptr);
    // layer 2
    gemm_xp<<<MTOT / 128, 256>>>(h1, WihL + 1 * HW, bih + 2 * HH, bhh + 2 * HH,
                                 xpb);
    rnn_scan<true, false><<<BB, 128>>>(xpb, h0, Whh + 2 * HW, nullptr, nullptr,
                                       nullptr);
    // layer 3: no hidden stores, FC fused into the scan epilogue
    gemm_xp<<<MTOT / 128, 256>>>(h0, WihL + 2 * HW, bih + 3 * HH, bhh + 3 * HH,
                                 xpb);
    rnn_scan<false, true><<<BB, 128>>>(xpb, nullptr, Whh + 3 * HW, fcw, fcb,
                                       out);
}

// round 14
// speedup vs baseline: 1.3560x; 1.1140x over previous
#include <cuda_runtime.h>
#include <cstdint>

#define BB 256
#define TT 1024
#define IDIM 2
#define HH 128
#define LL 4
#define MTOT (BB * TT)  // 262144

typedef unsigned long long ull;
typedef unsigned int u32;
typedef unsigned short u16;

// Scratch (device globals: allocation-free).
// h as bf16 hi/lo ushort planes (ping-pong); xp fp32 (+pad for cp.async ring).
__device__ u16 g_hhi[2][BB * TT * HH];
__device__ u16 g_hlo[2][BB * TT * HH];
__device__ float g_xp[BB * TT * HH + 8 * HH];
__device__ u16 g_whi[(LL - 1) * HH * HH];
__device__ u16 g_wlo[(LL - 1) * HH * HH];

__device__ __forceinline__ void ffma2(ull& acc, ull a, ull b) {
    asm("fma.rn.f32x2 %0, %1, %2, %0;" : "+l"(acc) : "l"(a), "l"(b));
}
__device__ __forceinline__ ull add2(ull a, ull b) {
    ull d;
    asm("add.rn.f32x2 %0, %1, %2;" : "=l"(d) : "l"(a), "l"(b));
    return d;
}
__device__ __forceinline__ void cp_async4(u32 saddr, const float* gptr) {
    asm volatile("cp.async.ca.shared.global [%0], [%1], 4;" ::"r"(saddr),
                 "l"(gptr)
                 : "memory");
}
__device__ __forceinline__ void cp_async16(u32 saddr, const void* gptr) {
    asm volatile("cp.async.cg.shared.global [%0], [%1], 16;" ::"r"(saddr),
                 "l"(gptr)
                 : "memory");
}
__device__ __forceinline__ void cp_commit() {
    asm volatile("cp.async.commit_group;" ::: "memory");
}
__device__ __forceinline__ void cp_wait6() {
    asm volatile("cp.async.wait_group 6;" ::: "memory");
}
__device__ __forceinline__ void cp_wait0() {
    asm volatile("cp.async.wait_group 0;" ::: "memory");
}

// round-to-nearest-even fp32 -> bf16 hi/lo split (bit ops, no header dep)
__device__ __forceinline__ void bf16_split(float v, u32& hi, u32& lo) {
    u32 xb = __float_as_uint(v);
    hi = (xb + 0x7fffu + ((xb >> 16) & 1u)) >> 16;
    float fhi = __uint_as_float(hi << 16);
    u32 lb = __float_as_uint(v - fhi);
    lo = (lb + 0x7fffu + ((lb >> 16) & 1u)) >> 16;
}

#define MMA_BF16(acc, a, b)                                                \
    asm volatile(                                                          \
        "mma.sync.aligned.m16n8k16.row.col.f32.bf16.bf16.f32 "             \
        "{%0,%1,%2,%3}, {%4,%5,%6,%7}, {%8,%9}, {%0,%1,%2,%3};"            \
        : "+f"((acc)[0]), "+f"((acc)[1]), "+f"((acc)[2]), "+f"((acc)[3])   \
        : "r"((a)[0]), "r"((a)[1]), "r"((a)[2]), "r"((a)[3]), "r"((b)[0]), \
          "r"((b)[1]))

// ---------------- one-shot W_ih -> bf16 hi/lo conversion ----------------
__global__ void wconv_kernel(const float* __restrict__ W, u16* __restrict__ whi,
                             u16* __restrict__ wlo, int n) {
    int i = blockIdx.x * 256 + threadIdx.x;
    if (i < n) {
        u32 hi, lo;
        bf16_split(W[i], hi, lo);
        whi[i] = (u16)hi;
        wlo[i] = (u16)lo;
    }
}

// ---------------- layer-0 input projection (I=2, trivial) ----------------
__global__ void proj0_kernel(const float* __restrict__ x,
                             const float* __restrict__ W0,
                             const float* __restrict__ bih,
                             const float* __restrict__ bhh,
                             float* __restrict__ xp) {
    int idx = blockIdx.x * 256 + threadIdx.x;
    int m = idx >> 7, j = idx & 127;
    float2 xv = *(const float2*)(x + m * 2);
    float2 w = *(const float2*)(W0 + j * 2);
    xp[idx] = fmaf(xv.x, w.x, fmaf(xv.y, w.y, bih[j] + bhh[j]));
}

// ---------------- tensor-core input-projection GEMM (layers 1..3) -------
// xp[m,n] = sum_k h[m,k]*W[n,k] + bias[n], via bf16 split:
//   C = Ahi*Whi + Ahi*Wlo + Alo*Whi   (fp32 accumulate)
// CTA tile 128(M) x 128(N), 8 warps (warp tile 64x32), K chunked x32,
// cp.async staging, plain-LDS fragment loads (documented lane mapping).
// Row stride 40 u16 = 80 B: multiple of 16 (cp.async16-legal on every row)
// and 20-bank stride keeps fragment LDS.32 conflict-free.
__global__ void __launch_bounds__(256, 2)
gemm_mma(const u16* __restrict__ Ahi_g, const u16* __restrict__ Alo_g,
         const u16* __restrict__ Whi_g, const u16* __restrict__ Wlo_g,
         const float* __restrict__ bih, const float* __restrict__ bhh,
         float* __restrict__ xp) {
    __shared__ __align__(16) u16 Ah[128][40], Al[128][40];  // [m][k]
    __shared__ __align__(16) u16 Wh[128][40], Wl[128][40];  // [n][k]

    const int tid = threadIdx.x;
    const int lane = tid & 31;
    const int wid = tid >> 5;
    const int m0 = blockIdx.x * 128;
    const int wm = (wid & 1) * 64;   // warp m offset
    const int wn = (wid >> 1) * 32;  // warp n offset

    float acc[4][4][4];
#pragma unroll
    for (int mi = 0; mi < 4; mi++)
#pragma unroll
        for (int ni = 0; ni < 4; ni++)
#pragma unroll
            for (int p = 0; p < 4; p++) acc[mi][ni][p] = 0.f;

    // per-lane bias for the epilogue columns
    float bias0[4], bias1[4];
#pragma unroll
    for (int ni = 0; ni < 4; ni++) {
        int n = wn + ni * 8 + (lane & 3) * 2;
        bias0[ni] = bih[n] + bhh[n];
        bias1[ni] = bih[n + 1] + bhh[n + 1];
    }

    // cp.async staging: 2048 16B chunks per k-chunk / 256 thr = 8 each.
    // flat = it*256+tid: plane = flat>>9 (0:Ah 1:Al 2:Wh 3:Wl),
    // s = flat&511: row = s>>2, q = s&3 (16B sub-chunk).
    u32 sbase[8];
    const u16* gbase[8];
#pragma unroll
    for (int it = 0; it < 8; it++) {
        int flat = it * 256 + tid;
        int plane = flat >> 9;
        int s = flat & 511;
        int row = s >> 2, q = s & 3;
        u16* sp = (plane == 0)   ? &Ah[row][q * 8]
                  : (plane == 1) ? &Al[row][q * 8]
                  : (plane == 2) ? &Wh[row][q * 8]
                                 : &Wl[row][q * 8];
        sbase[it] = (u32)__cvta_generic_to_shared(sp);
        const u16* gp = (plane == 0)   ? Ahi_g + (size_t)(m0 + row) * HH
                        : (plane == 1) ? Alo_g + (size_t)(m0 + row) * HH
                        : (plane == 2) ? Whi_g + (size_t)row * HH
                                       : Wlo_g + (size_t)row * HH;
        gbase[it] = gp + q * 8;
    }

    for (int kc = 0; kc < 4; kc++) {
#pragma unroll
        for (int it = 0; it < 8; it++)
            cp_async16(sbase[it], gbase[it] + kc * 32);
        cp_commit();
        cp_wait0();
        __syncthreads();

#pragma unroll
        for (int ks = 0; ks < 32; ks += 16) {
            const int fr = lane >> 2;            // frag row/col within tile
            const int fc = ks + (lane & 3) * 2;  // frag k pair
            u32 bh[4][2], bl[4][2];
#pragma unroll
            for (int ni = 0; ni < 4; ni++) {
                int n = wn + ni * 8 + fr;
                bh[ni][0] = *(const u32*)&Wh[n][fc];
                bh[ni][1] = *(const u32*)&Wh[n][fc + 8];
                bl[ni][0] = *(const u32*)&Wl[n][fc];
                bl[ni][1] = *(const u32*)&Wl[n][fc + 8];
            }
#pragma unroll
            for (int mi = 0; mi < 4; mi++) {
                int r = wm + mi * 16 + fr;
                u32 ah[4], al[4];
                ah[0] = *(const u32*)&Ah[r][fc];
                ah[1] = *(const u32*)&Ah[r + 8][fc];
                ah[2] = *(const u32*)&Ah[r][fc + 8];
                ah[3] = *(const u32*)&Ah[r + 8][fc + 8];
                al[0] = *(const u32*)&Al[r][fc];
                al[1] = *(const u32*)&Al[r + 8][fc];
                al[2] = *(const u32*)&Al[r][fc + 8];
                al[3] = *(const u32*)&Al[r + 8][fc + 8];
#pragma unroll
                for (int ni = 0; ni < 4; ni++) {
                    MMA_BF16(acc[mi][ni], ah, bh[ni]);
                    MMA_BF16(acc[mi][ni], ah, bl[ni]);
                    MMA_BF16(acc[mi][ni], al, bh[ni]);
                }
            }
        }
        __syncthreads();
    }

    // epilogue: c-frag lane mapping: c0,c1 = (row, col:col+1); c2,c3 = row+8
#pragma unroll
    for (int mi = 0; mi < 4; mi++) {
        int mrow = m0 + wm + mi * 16 + (lane >> 2);
#pragma unroll
        for (int ni = 0; ni < 4; ni++) {
            int ncol = wn + ni * 8 + (lane & 3) * 2;
            float2 v0 = make_float2(acc[mi][ni][0] + bias0[ni],
                                    acc[mi][ni][1] + bias1[ni]);
            float2 v1 = make_float2(acc[mi][ni][2] + bias0[ni],
                                    acc[mi][ni][3] + bias1[ni]);
            *(float2*)&xp[(size_t)mrow * HH + ncol] = v0;
            *(float2*)&xp[(size_t)(mrow + 8) * HH + ncol] = v1;
        }
    }
}

// ---------------- recurrent scan (R11, proven) + bf16 hi/lo output ------
template <bool STORE, bool FC>
__global__ void __launch_bounds__(128, 2)
rnn_scan(const float* __restrict__ xp, u16* __restrict__ ohi,
         u16* __restrict__ olo, const float* __restrict__ Whh,
         const float* __restrict__ fcw, const float* __restrict__ fcb,
         float* __restrict__ fc_out) {
    __shared__ __align__(16) float hbuf[2][HH];
    __shared__ __align__(16) float xpring[8][HH];
    __shared__ float red[4];

    const int j = threadIdx.x;
    const int b = blockIdx.x;

    ull w[64];
    {
        const ull* wp = (const ull*)(Whh + j * HH);
#pragma unroll
        for (int i = 0; i < 64; i++) w[i] = wp[i];
    }

    hbuf[0][j] = 0.f;

    const float* xptr = xp + (size_t)b * TT * HH + j;
    u16* ohp = ohi + (size_t)b * TT * HH + j;
    u16* olp = olo + (size_t)b * TT * HH + j;

    u32 ring_s[8];
#pragma unroll
    for (int i = 0; i < 8; i++)
        ring_s[i] = (u32)__cvta_generic_to_shared(&xpring[i][j]);
#pragma unroll
    for (int i = 0; i < 7; i++) {
        cp_async4(ring_s[i], xptr + (size_t)i * HH);
        cp_commit();
    }
    const float* xf = xptr + 7 * HH;
    __syncthreads();

    float lh = 0.f;
    int buf = 0;
    for (int t = 0; t < TT; t++) {
        cp_wait6();
        float xv = xpring[t & 7][j];

        const ulonglong2* hp = (const ulonglong2*)hbuf[buf];
        ull a0 = 0ULL, a1 = 0ULL, a2 = 0ULL, a3 = 0ULL;
#pragma unroll
        for (int q = 0; q < 32; q += 4) {
            ulonglong2 u0 = hp[q];
            ulonglong2 u1 = hp[q + 1];
            ulonglong2 u2 = hp[q + 2];
            ulonglong2 u3 = hp[q + 3];
            ffma2(a0, u0.x, w[2 * q + 0]);
            ffma2(a0, u0.y, w[2 * q + 1]);
            ffma2(a1, u1.x, w[2 * q + 2]);
            ffma2(a1, u1.y, w[2 * q + 3]);
            ffma2(a2, u2.x, w[2 * q + 4]);
            ffma2(a2, u2.y, w[2 * q + 5]);
            ffma2(a3, u3.x, w[2 * q + 6]);
            ffma2(a3, u3.y, w[2 * q + 7]);
        }
        ull s = add2(add2(a0, a1), add2(a2, a3));
        float2 f = *(float2*)&s;
        float h = fmaxf(f.x + f.y + xv, 0.f);

        hbuf[buf ^ 1][j] = h;
        if (STORE) {
            u32 hi, lo;
            bf16_split(h, hi, lo);
            ohp[0] = (u16)hi;
            olp[0] = (u16)lo;
            ohp += HH;
            olp += HH;
        }
        if (FC) lh = h;

        cp_async4(ring_s[(t + 7) & 7], xf);
        cp_commit();
        xf += HH;

        buf ^= 1;
        __syncthreads();
    }

    if (FC) {
        float v = lh * fcw[j];
#pragma unroll
        for (int o = 16; o > 0; o >>= 1)
            v += __shfl_down_sync(0xffffffffu, v, o);
        if ((j & 31) == 0) red[j >> 5] = v;
        __syncthreads();
        if (j == 0) fc_out[b] = red[0] + red[1] + red[2] + red[3] + fcb[0];
    }
}

extern "C" void kernel_launch(void* const* d_in, const int* in_sizes, int n_in,
                              void* d_out, int out_size) {
    const float* x    = (const float*)d_in[0];  // [B,T,I]
    const float* Wih0 = (const float*)d_in[1];  // [H,I]
    const float* WihL = (const float*)d_in[2];  // [L-1,H,H]
    const float* Whh  = (const float*)d_in[3];  // [L,H,H]
    const float* bih  = (const float*)d_in[4];  // [L,H]
    const float* bhh  = (const float*)d_in[5];  // [L,H]
    const float* fcw  = (const float*)d_in[6];  // [C,H]
    const float* fcb  = (const float*)d_in[7];  // [C]
    float* out = (float*)d_out;                 // [B,C] = [256,1]

    float* xpb;
    u16 *hhi, *hlo, *whi, *wlo;
    cudaGetSymbolAddress((void**)&xpb, g_xp);
    cudaGetSymbolAddress((void**)&hhi, g_hhi);
    cudaGetSymbolAddress((void**)&hlo, g_hlo);
    cudaGetSymbolAddress((void**)&whi, g_whi);
    cudaGetSymbolAddress((void**)&wlo, g_wlo);

    const int HW = HH * HH;
    const size_t HP = (size_t)BB * TT * HH;  // one h plane

    // one-shot W_ih conversion (layers 1..3)
    wconv_kernel<<<(3 * HW + 255) / 256, 256>>>(WihL, whi, wlo, 3 * HW);

    // layer 0
    proj0_kernel<<<(MTOT * HH) / 256, 256>>>(x, Wih0, bih, bhh, xpb);
    rnn_scan<true, false><<<BB, 128>>>(xpb, hhi, hlo, Whh + 0 * HW, nullptr,
                                       nullptr, nullptr);
    // layer 1
    gemm_mma<<<MTOT / 128, 256>>>(hhi, hlo, whi + 0 * HW, wlo + 0 * HW,
                                  bih + 1 * HH, bhh + 1 * HH, xpb);
    rnn_scan<true, false><<<BB, 128>>>(xpb, hhi + HP, hlo + HP, Whh + 1 * HW,
                                       nullptr, nullptr, nullptr);
    // layer 2
    gemm_mma<<<MTOT / 128, 256>>>(hhi + HP, hlo + HP, whi + 1 * HW,
                                  wlo + 1 * HW, bih + 2 * HH, bhh + 2 * HH,
                                  xpb);
    rnn_scan<true, false><<<BB, 128>>>(xpb, hhi, hlo, Whh + 2 * HW, nullptr,
                                       nullptr, nullptr);
    // layer 3
    gemm_mma<<<MTOT / 128, 256>>>(hhi, hlo, whi + 2 * HW, wlo + 2 * HW,
                                  bih + 3 * HH, bhh + 3 * HH, xpb);
    rnn_scan<false, true><<<BB, 128>>>(xpb, nullptr, nullptr, Whh + 3 * HW,
                                       fcw, fcb, out);
}

// round 16
// speedup vs baseline: 1.4380x; 1.0605x over previous
#include <cuda_runtime.h>
#include <cstdint>

#define BB 256
#define TT 1024
#define IDIM 2
#define HH 128
#define LL 4
#define MTOT (BB * TT)  // 262144

typedef unsigned long long ull;
typedef unsigned int u32;
typedef unsigned short u16;

// Scratch (device globals: allocation-free).
// h as bf16 hi/lo ushort planes (ping-pong); xp fp32 (+pad for cp.async ring).
__device__ u16 g_hhi[2][BB * TT * HH];
__device__ u16 g_hlo[2][BB * TT * HH];
__device__ float g_xp[BB * TT * HH + 8 * HH];
__device__ u16 g_whi[(LL - 1) * HH * HH];
__device__ u16 g_wlo[(LL - 1) * HH * HH];

__device__ __forceinline__ void ffma2(ull& acc, ull a, ull b) {
    asm("fma.rn.f32x2 %0, %1, %2, %0;" : "+l"(acc) : "l"(a), "l"(b));
}
__device__ __forceinline__ ull add2(ull a, ull b) {
    ull d;
    asm("add.rn.f32x2 %0, %1, %2;" : "=l"(d) : "l"(a), "l"(b));
    return d;
}
__device__ __forceinline__ void cp_async4(u32 saddr, const float* gptr) {
    asm volatile("cp.async.ca.shared.global [%0], [%1], 4;" ::"r"(saddr),
                 "l"(gptr)
                 : "memory");
}
__device__ __forceinline__ void cp_async8(u32 saddr, const float* gptr) {
    asm volatile("cp.async.ca.shared.global [%0], [%1], 8;" ::"r"(saddr),
                 "l"(gptr)
                 : "memory");
}
__device__ __forceinline__ void cp_async16(u32 saddr, const void* gptr) {
    asm volatile("cp.async.cg.shared.global [%0], [%1], 16;" ::"r"(saddr),
                 "l"(gptr)
                 : "memory");
}
__device__ __forceinline__ void cp_commit() {
    asm volatile("cp.async.commit_group;" ::: "memory");
}
__device__ __forceinline__ void cp_wait6() {
    asm volatile("cp.async.wait_group 6;" ::: "memory");
}
__device__ __forceinline__ void cp_wait1() {
    asm volatile("cp.async.wait_group 1;" ::: "memory");
}
__device__ __forceinline__ void cp_wait0() {
    asm volatile("cp.async.wait_group 0;" ::: "memory");
}

// round-to-nearest-even fp32 -> bf16 hi/lo split (bit ops, no header dep)
__device__ __forceinline__ void bf16_split(float v, u32& hi, u32& lo) {
    u32 xb = __float_as_uint(v);
    hi = (xb + 0x7fffu + ((xb >> 16) & 1u)) >> 16;
    float fhi = __uint_as_float(hi << 16);
    u32 lb = __float_as_uint(v - fhi);
    lo = (lb + 0x7fffu + ((lb >> 16) & 1u)) >> 16;
}

#define MMA_BF16(acc, a, b)                                                \
    asm volatile(                                                          \
        "mma.sync.aligned.m16n8k16.row.col.f32.bf16.bf16.f32 "             \
        "{%0,%1,%2,%3}, {%4,%5,%6,%7}, {%8,%9}, {%0,%1,%2,%3};"            \
        : "+f"((acc)[0]), "+f"((acc)[1]), "+f"((acc)[2]), "+f"((acc)[3])   \
        : "r"((a)[0]), "r"((a)[1]), "r"((a)[2]), "r"((a)[3]), "r"((b)[0]), \
          "r"((b)[1]))

// ---------------- one-shot W_ih -> bf16 hi/lo conversion ----------------
__global__ void wconv_kernel(const float* __restrict__ W, u16* __restrict__ whi,
                             u16* __restrict__ wlo, int n) {
    int i = blockIdx.x * 256 + threadIdx.x;
    if (i < n) {
        u32 hi, lo;
        bf16_split(W[i], hi, lo);
        whi[i] = (u16)hi;
        wlo[i] = (u16)lo;
    }
}

// ---------------- tensor-core input-projection GEMM (layers 1..3) -------
// xp[m,n] = sum_k h[m,k]*W[n,k] + bias[n], via bf16 split:
//   C = Ahi*Whi + Ahi*Wlo + Alo*Whi   (fp32 accumulate)
// CTA tile 128(M) x 128(N), 8 warps (warp tile 64x32).
// DOUBLE-BUFFERED K pipeline in DYNAMIC smem (80 KB > 48 KB static cap):
// chunk kc+1 streams via cp.async while chunk kc runs on the tensor pipe.
// Row stride 40 u16 = 80 B (cp.async16-legal every row, conflict-free LDS).
// Plane layout in dsm (u16 elements): (st*4 + plane)*5120 + row*40.
#define PLANE_E 5120  // 128*40 u16 elements per array
#define GEMM_SMEM (16 * PLANE_E * sizeof(u16))  // 2 stages * 4 planes * 2 halves? no: 8 arrays = 81920 B

__global__ void __launch_bounds__(256, 2)
gemm_mma(const u16* __restrict__ Ahi_g, const u16* __restrict__ Alo_g,
         const u16* __restrict__ Whi_g, const u16* __restrict__ Wlo_g,
         const float* __restrict__ bih, const float* __restrict__ bhh,
         float* __restrict__ xp) {
    extern __shared__ __align__(16) u16 dsm[];
    // array base (elements): stage st, plane p (0:Ah 1:Al 2:Wh 3:Wl)
#define SMP(st, p) (dsm + ((st) * 4 + (p)) * PLANE_E)
    const u32 STB = 4 * PLANE_E * 2;  // byte offset between stages

    const int tid = threadIdx.x;
    const int lane = tid & 31;
    const int wid = tid >> 5;
    const int m0 = blockIdx.x * 128;
    const int wm = (wid & 1) * 64;   // warp m offset
    const int wn = (wid >> 1) * 32;  // warp n offset

    float acc[4][4][4];
#pragma unroll
    for (int mi = 0; mi < 4; mi++)
#pragma unroll
        for (int ni = 0; ni < 4; ni++)
#pragma unroll
            for (int p = 0; p < 4; p++) acc[mi][ni][p] = 0.f;

    // per-lane bias for the epilogue columns
    float bias0[4], bias1[4];
#pragma unroll
    for (int ni = 0; ni < 4; ni++) {
        int n = wn + ni * 8 + (lane & 3) * 2;
        bias0[ni] = bih[n] + bhh[n];
        bias1[ni] = bih[n + 1] + bhh[n + 1];
    }

    // cp.async staging: 2048 16B chunks per k-chunk / 256 thr = 8 each.
    // flat = it*256+tid: plane = flat>>9, s = flat&511: row = s>>2, q = s&3.
    u32 sbase[8];
    const u16* gbase[8];
#pragma unroll
    for (int it = 0; it < 8; it++) {
        int flat = it * 256 + tid;
        int plane = flat >> 9;
        int s = flat & 511;
        int row = s >> 2, q = s & 3;
        u16* sp = SMP(0, plane) + row * 40 + q * 8;
        sbase[it] = (u32)__cvta_generic_to_shared(sp);
        const u16* gp = (plane == 0)   ? Ahi_g + (size_t)(m0 + row) * HH
                        : (plane == 1) ? Alo_g + (size_t)(m0 + row) * HH
                        : (plane == 2) ? Whi_g + (size_t)row * HH
                                       : Wlo_g + (size_t)row * HH;
        gbase[it] = gp + q * 8;
    }

#define GEMM_LOADS(kc, st)                                                \
    do {                                                                  \
        _Pragma("unroll") for (int it = 0; it < 8; it++)                  \
            cp_async16(sbase[it] + (st) * STB, gbase[it] + (kc) * 32);    \
        cp_commit();                                                      \
    } while (0)

    GEMM_LOADS(0, 0);
    GEMM_LOADS(1, 1);

    for (int kc = 0; kc < 4; kc++) {
        if (kc < 3)
            cp_wait1();
        else
            cp_wait0();
        __syncthreads();
        const int st = kc & 1;
        const u16* Ah = SMP(st, 0);
        const u16* Al = SMP(st, 1);
        const u16* Wh = SMP(st, 2);
        const u16* Wl = SMP(st, 3);

#pragma unroll
        for (int ks = 0; ks < 32; ks += 16) {
            const int fr = lane >> 2;            // frag row/col within tile
            const int fc = ks + (lane & 3) * 2;  // frag k pair
            u32 bh[4][2], bl[4][2];
#pragma unroll
            for (int ni = 0; ni < 4; ni++) {
                int n = wn + ni * 8 + fr;
                bh[ni][0] = *(const u32*)&Wh[n * 40 + fc];
                bh[ni][1] = *(const u32*)&Wh[n * 40 + fc + 8];
                bl[ni][0] = *(const u32*)&Wl[n * 40 + fc];
                bl[ni][1] = *(const u32*)&Wl[n * 40 + fc + 8];
            }
#pragma unroll
            for (int mi = 0; mi < 4; mi++) {
                int r = wm + mi * 16 + fr;
                u32 ah[4], al[4];
                ah[0] = *(const u32*)&Ah[r * 40 + fc];
                ah[1] = *(const u32*)&Ah[(r + 8) * 40 + fc];
                ah[2] = *(const u32*)&Ah[r * 40 + fc + 8];
                ah[3] = *(const u32*)&Ah[(r + 8) * 40 + fc + 8];
                al[0] = *(const u32*)&Al[r * 40 + fc];
                al[1] = *(const u32*)&Al[(r + 8) * 40 + fc];
                al[2] = *(const u32*)&Al[r * 40 + fc + 8];
                al[3] = *(const u32*)&Al[(r + 8) * 40 + fc + 8];
#pragma unroll
                for (int ni = 0; ni < 4; ni++) {
                    MMA_BF16(acc[mi][ni], ah, bh[ni]);
                    MMA_BF16(acc[mi][ni], ah, bl[ni]);
                    MMA_BF16(acc[mi][ni], al, bh[ni]);
                }
            }
        }
        __syncthreads();  // stage st fully consumed
        if (kc < 2) GEMM_LOADS(kc + 2, st);
    }

    // epilogue: c-frag lane mapping: c0,c1 = (row, col:col+1); c2,c3 = row+8
#pragma unroll
    for (int mi = 0; mi < 4; mi++) {
        int mrow = m0 + wm + mi * 16 + (lane >> 2);
#pragma unroll
        for (int ni = 0; ni < 4; ni++) {
            int ncol = wn + ni * 8 + (lane & 3) * 2;
            float2 v0 = make_float2(acc[mi][ni][0] + bias0[ni],
                                    acc[mi][ni][1] + bias1[ni]);
            float2 v1 = make_float2(acc[mi][ni][2] + bias0[ni],
                                    acc[mi][ni][3] + bias1[ni]);
            *(float2*)&xp[(size_t)mrow * HH + ncol] = v0;
            *(float2*)&xp[(size_t)(mrow + 8) * HH + ncol] = v1;
        }
    }
}

// ---------------- recurrent scan (proven R13 body) -----------------------
// PROJ: layer 0 fuses the I=2 input projection (wi0/wi1/bias in regs; x
// streams through a tiny smem ring, cp.async8 by thread 0, uniform LDS.64
// consume; pointer clamped at T). Removes the proj0 kernel + 256 MB of
// xp traffic. STORE: emit h as bf16 hi/lo planes. FC: fuse the C=1 head.
template <bool STORE, bool FC, bool PROJ>
__global__ void __launch_bounds__(128, 2)
rnn_scan(const float* __restrict__ xp, const float* __restrict__ x,
         const float* __restrict__ W0, const float* __restrict__ bih0,
         const float* __restrict__ bhh0, u16* __restrict__ ohi,
         u16* __restrict__ olo, const float* __restrict__ Whh,
         const float* __restrict__ fcw, const float* __restrict__ fcb,
         float* __restrict__ fc_out) {
    __shared__ __align__(16) float hbuf[2][HH];
    __shared__ __align__(16) float xpring[8][HH];
    __shared__ __align__(16) float xr[8][2];
    __shared__ float red[4];

    const int j = threadIdx.x;
    const int b = blockIdx.x;

    ull w[64];
    {
        const ull* wp = (const ull*)(Whh + j * HH);
#pragma unroll
        for (int i = 0; i < 64; i++) w[i] = wp[i];
    }

    float wi0 = 0.f, wi1 = 0.f, bj = 0.f;
    const float* xsrc = nullptr;
    if (PROJ) {
        wi0 = W0[j * 2 + 0];
        wi1 = W0[j * 2 + 1];
        bj = bih0[j] + bhh0[j];
        xsrc = x + (size_t)b * TT * IDIM;
    }

    hbuf[0][j] = 0.f;

    const float* xptr = PROJ ? nullptr : (xp + (size_t)b * TT * HH + j);
    u16* ohp = ohi + (size_t)b * TT * HH + j;
    u16* olp = olo + (size_t)b * TT * HH + j;

    u32 ring_s[8], xr_s[8];
#pragma unroll
    for (int i = 0; i < 8; i++) {
        ring_s[i] = (u32)__cvta_generic_to_shared(&xpring[i][j]);
        xr_s[i] = (u32)__cvta_generic_to_shared(&xr[i][0]);
    }
    // prefill 7 groups (uniform group count across threads)
#pragma unroll
    for (int i = 0; i < 7; i++) {
        if (PROJ) {
            if (j == 0) cp_async8(xr_s[i], xsrc + i * IDIM);
        } else {
            cp_async4(ring_s[i], xptr + (size_t)i * HH);
        }
        cp_commit();
    }
    const float* xf = PROJ ? nullptr : (xptr + 7 * HH);
    cp_wait6();
    __syncthreads();

    float lh = 0.f;
    int buf = 0;
    for (int t = 0; t < TT; t++) {
        // consume slot t (guaranteed by wait6 before last barrier)
        float xv;
        if (PROJ) {
            float2 xx = *(const float2*)xr[t & 7];
            xv = fmaf(xx.y, wi1, fmaf(xx.x, wi0, bj));
        } else {
            xv = xpring[t & 7][j];
        }

        const ulonglong2* hp = (const ulonglong2*)hbuf[buf];
        ull a0 = 0ULL, a1 = 0ULL, a2 = 0ULL, a3 = 0ULL;
#pragma unroll
        for (int q = 0; q < 32; q += 4) {
            ulonglong2 u0 = hp[q];
            ulonglong2 u1 = hp[q + 1];
            ulonglong2 u2 = hp[q + 2];
            ulonglong2 u3 = hp[q + 3];
            ffma2(a0, u0.x, w[2 * q + 0]);
            ffma2(a0, u0.y, w[2 * q + 1]);
            ffma2(a1, u1.x, w[2 * q + 2]);
            ffma2(a1, u1.y, w[2 * q + 3]);
            ffma2(a2, u2.x, w[2 * q + 4]);
            ffma2(a2, u2.y, w[2 * q + 5]);
            ffma2(a3, u3.x, w[2 * q + 6]);
            ffma2(a3, u3.y, w[2 * q + 7]);
        }
        ull s = add2(add2(a0, a1), add2(a2, a3));
        float2 f = *(float2*)&s;
        float h = fmaxf(f.x + f.y + xv, 0.f);

        hbuf[buf ^ 1][j] = h;
        if (STORE) {
            u32 hi, lo;
            bf16_split(h, hi, lo);
            ohp[0] = (u16)hi;
            olp[0] = (u16)lo;
            ohp += HH;
            olp += HH;
        }
        if (FC) lh = h;

        // prefetch slot t+7; ensure slot t+1 complete before the barrier
        if (PROJ) {
            int tf = t + 7 < TT ? t + 7 : TT - 1;  // clamp: no OOB on x
            if (j == 0) cp_async8(xr_s[(t + 7) & 7], xsrc + tf * IDIM);
        } else {
            cp_async4(ring_s[(t + 7) & 7], xf);  // g_xp padded: safe overrun
            xf += HH;
        }
        cp_commit();
        cp_wait6();

        buf ^= 1;
        __syncthreads();
    }

    if (FC) {
        float v = lh * fcw[j];
#pragma unroll
        for (int o = 16; o > 0; o >>= 1)
            v += __shfl_down_sync(0xffffffffu, v, o);
        if ((j & 31) == 0) red[j >> 5] = v;
        __syncthreads();
        if (j == 0) fc_out[b] = red[0] + red[1] + red[2] + red[3] + fcb[0];
    }
}

extern "C" void kernel_launch(void* const* d_in, const int* in_sizes, int n_in,
                              void* d_out, int out_size) {
    const float* x    = (const float*)d_in[0];  // [B,T,I]
    const float* Wih0 = (const float*)d_in[1];  // [H,I]
    const float* WihL = (const float*)d_in[2];  // [L-1,H,H]
    const float* Whh  = (const float*)d_in[3];  // [L,H,H]
    const float* bih  = (const float*)d_in[4];  // [L,H]
    const float* bhh  = (const float*)d_in[5];  // [L,H]
    const float* fcw  = (const float*)d_in[6];  // [C,H]
    const float* fcb  = (const float*)d_in[7];  // [C]
    float* out = (float*)d_out;                 // [B,C] = [256,1]

    float* xpb;
    u16 *hhi, *hlo, *whi, *wlo;
    cudaGetSymbolAddress((void**)&xpb, g_xp);
    cudaGetSymbolAddress((void**)&hhi, g_hhi);
    cudaGetSymbolAddress((void**)&hlo, g_hlo);
    cudaGetSymbolAddress((void**)&whi, g_whi);
    cudaGetSymbolAddress((void**)&wlo, g_wlo);

    const int HW = HH * HH;
    const size_t HP = (size_t)BB * TT * HH;  // one h plane
    const int GSM = 8 * PLANE_E * sizeof(u16);  // 81920 B dynamic smem

    // opt-in to >48KB dynamic smem (attribute set; not an allocation)
    cudaFuncSetAttribute(gemm_mma, cudaFuncAttributeMaxDynamicSharedMemorySize,
                         GSM);

    // one-shot W_ih conversion (layers 1..3)
    wconv_kernel<<<(3 * HW + 255) / 256, 256>>>(WihL, whi, wlo, 3 * HW);

    // layer 0: proj fused into the scan
    rnn_scan<true, false, true><<<BB, 128>>>(nullptr, x, Wih0, bih, bhh, hhi,
                                             hlo, Whh + 0 * HW, nullptr,
                                             nullptr, nullptr);
    // layer 1
    gemm_mma<<<MTOT / 128, 256, GSM>>>(hhi, hlo, whi + 0 * HW, wlo + 0 * HW,
                                       bih + 1 * HH, bhh + 1 * HH, xpb);
    rnn_scan<true, false, false><<<BB, 128>>>(xpb, nullptr, nullptr, nullptr,
                                              nullptr, hhi + HP, hlo + HP,
                                              Whh + 1 * HW, nullptr, nullptr,
                                              nullptr);
    // layer 2
    gemm_mma<<<MTOT / 128, 256, GSM>>>(hhi + HP, hlo + HP, whi + 1 * HW,
                                       wlo + 1 * HW, bih + 2 * HH,
                                       bhh + 2 * HH, xpb);
    rnn_scan<true, false, false><<<BB, 128>>>(xpb, nullptr, nullptr, nullptr,
                                              nullptr, hhi, hlo, Whh + 2 * HW,
                                              nullptr, nullptr, nullptr);
    // layer 3: no hidden stores, FC fused
    gemm_mma<<<MTOT / 128, 256, GSM>>>(hhi, hlo, whi + 2 * HW, wlo + 2 * HW,
                                       bih + 3 * HH, bhh + 3 * HH, xpb);
    rnn_scan<false, true, false><<<BB, 128>>>(xpb, nullptr, nullptr, nullptr,
                                              nullptr, nullptr, nullptr,
                                              Whh + 3 * HW, fcw, fcb, out);
}